// round 2
// baseline (speedup 1.0000x reference)
#include <cuda_runtime.h>
#include <math.h>

// ----------------------------------------------------------------------------
// LSTM_88210038325547: 2-layer LSTM cell + MLP head, fp32.
//   B=8192, D=512, H=1024, DM=2048, O=256
// Outputs (flattened, concatenated in reference return order):
//   out [B,O], h0n [B,H], h1n [B,H], c0n [B,H], c1n [B,H]
// ----------------------------------------------------------------------------

#define BB   8192
#define DD   512
#define HH   1024
#define DMM  2048
#define OO   256

#define BM 128
#define BN 128
#define BK 8
#define TM 8
#define TN 8
#define NT 256

// Scratch (static device memory: allocation-guard safe)
__device__ float g_gbuf[(size_t)BB * 4096];   // gate pre-activations (134 MB)
__device__ float g_tbuf[(size_t)BB * DMM];    // MLP hidden (64 MB)

struct GemmArgs {
    // A = [seg0 | seg1], each segment row-major [M, Kx], optional per-element mask
    const float* A0; const float* Ma0; int K0;
    const float* A1; const float* Ma1; int K1;
    // per-gate weights [K, Nper] row-major, and per-gate bias [Nper]
    const float* W0; const float* W1; const float* W2; const float* W3;
    const float* b0; const float* b1; const float* b2; const float* b3;
    int Nper;      // column width per gate block (BN divides Nper)
    float* C;      // [M, N] row-major
    int N;
};

__global__ __launch_bounds__(NT, 2)
void gemm_kernel(GemmArgs ga) {
    __shared__ float As[2][BK][BM];
    __shared__ float Bs[2][BK][BN];

    const int tid    = threadIdx.x;
    const int m_base = blockIdx.y * BM;
    const int n_base = blockIdx.x * BN;

    const int gate = n_base / ga.Nper;          // whole BN tile lies in one gate
    const int wcol = n_base % ga.Nper;
    const float* W    = (gate == 0) ? ga.W0 : (gate == 1) ? ga.W1 : (gate == 2) ? ga.W2 : ga.W3;
    const float* bias = (gate == 0) ? ga.b0 : (gate == 1) ? ga.b1 : (gate == 2) ? ga.b2 : ga.b3;

    const int K = ga.K0 + ga.K1;

    // A tile loader: 128 rows x 8 k per stage; thread -> (row, 4 consecutive k)
    const int ar   = tid >> 1;
    const int ak   = (tid & 1) * 4;
    const int arow = m_base + ar;
    // B tile loader: 8 k-rows x 128 n; thread -> (k-row, 4 consecutive n)
    const int br = tid >> 5;
    const int bc = (tid & 31) * 4;
    // compute sub-tile
    const int tm = (tid >> 4) * TM;
    const int tn = (tid & 15) * TN;

    float acc[TM][TN];
#pragma unroll
    for (int i = 0; i < TM; i++)
#pragma unroll
        for (int j = 0; j < TN; j++) acc[i][j] = 0.f;

    auto loadA = [&](int kt) -> float4 {
        const int k = kt + ak;   // 4-chunk never straddles seg boundary (K0 % 4 == 0)
        float4 v;
        if (k < ga.K0) {
            const size_t off = (size_t)arow * ga.K0 + k;
            v = *(const float4*)(ga.A0 + off);
            if (ga.Ma0) {
                float4 m = *(const float4*)(ga.Ma0 + off);
                v.x *= m.x; v.y *= m.y; v.z *= m.z; v.w *= m.w;
            }
        } else {
            const size_t off = (size_t)arow * ga.K1 + (k - ga.K0);
            v = *(const float4*)(ga.A1 + off);
            if (ga.Ma1) {
                float4 m = *(const float4*)(ga.Ma1 + off);
                v.x *= m.x; v.y *= m.y; v.z *= m.z; v.w *= m.w;
            }
        }
        return v;
    };
    auto loadB = [&](int kt) -> float4 {
        return *(const float4*)(W + (size_t)(kt + br) * ga.Nper + wcol + bc);
    };

    // stage 0
    {
        float4 a = loadA(0);
        float4 b = loadB(0);
        As[0][ak + 0][ar] = a.x; As[0][ak + 1][ar] = a.y;
        As[0][ak + 2][ar] = a.z; As[0][ak + 3][ar] = a.w;
        *(float4*)&Bs[0][br][bc] = b;
    }
    __syncthreads();

    const int ntiles = K / BK;
    for (int t = 0; t < ntiles; t++) {
        const int buf = t & 1;
        float4 a = make_float4(0.f, 0.f, 0.f, 0.f);
        float4 b = make_float4(0.f, 0.f, 0.f, 0.f);
        const bool more = (t + 1 < ntiles);
        if (more) { a = loadA((t + 1) * BK); b = loadB((t + 1) * BK); }

#pragma unroll
        for (int k = 0; k < BK; k++) {
            float ra[TM], rb[TN];
            *(float4*)&ra[0] = *(const float4*)&As[buf][k][tm];
            *(float4*)&ra[4] = *(const float4*)&As[buf][k][tm + 4];
            *(float4*)&rb[0] = *(const float4*)&Bs[buf][k][tn];
            *(float4*)&rb[4] = *(const float4*)&Bs[buf][k][tn + 4];
#pragma unroll
            for (int i = 0; i < TM; i++)
#pragma unroll
                for (int j = 0; j < TN; j++)
                    acc[i][j] = fmaf(ra[i], rb[j], acc[i][j]);
        }

        if (more) {
            const int nb = buf ^ 1;
            As[nb][ak + 0][ar] = a.x; As[nb][ak + 1][ar] = a.y;
            As[nb][ak + 2][ar] = a.z; As[nb][ak + 3][ar] = a.w;
            *(float4*)&Bs[nb][br][bc] = b;
            __syncthreads();
        }
    }

    // epilogue: + bias, store
    float bfrag[TN];
#pragma unroll
    for (int j = 0; j < TN; j++) bfrag[j] = bias[wcol + tn + j];

#pragma unroll
    for (int i = 0; i < TM; i++) {
        const size_t row = (size_t)(m_base + tm + i);
#pragma unroll
        for (int j = 0; j < TN; j += 4) {
            float4 v;
            v.x = acc[i][j + 0] + bfrag[j + 0];
            v.y = acc[i][j + 1] + bfrag[j + 1];
            v.z = acc[i][j + 2] + bfrag[j + 2];
            v.w = acc[i][j + 3] + bfrag[j + 3];
            *(float4*)&ga.C[row * ga.N + n_base + tn + j] = v;
        }
    }
}

// ----------------------------------------------------------------------------
// Elementwise LSTM cell: g = [f|i|ct|o] (each H wide), c -> h_new, c_new
// ----------------------------------------------------------------------------
__device__ __forceinline__ float sigf(float x) { return 1.f / (1.f + __expf(-x)); }

__global__ void lstm_cell_kernel(const float* __restrict__ g,
                                 const float* __restrict__ c,
                                 float* __restrict__ h_out,
                                 float* __restrict__ c_out) {
    const int idx = blockIdx.x * blockDim.x + threadIdx.x;   // over B*H/4
    const int r  = idx >> 8;                                 // H/4 = 256 per row
    const int j  = (idx & 255) << 2;
    const size_t gb = (size_t)r * 4096 + j;
    const float4 f4 = *(const float4*)&g[gb];
    const float4 i4 = *(const float4*)&g[gb + 1024];
    const float4 t4 = *(const float4*)&g[gb + 2048];
    const float4 o4 = *(const float4*)&g[gb + 3072];
    const float4 c4 = *(const float4*)&c[(size_t)r * HH + j];

    float4 cn, hn;
    cn.x = sigf(f4.x) * c4.x + sigf(i4.x) * tanhf(t4.x);
    cn.y = sigf(f4.y) * c4.y + sigf(i4.y) * tanhf(t4.y);
    cn.z = sigf(f4.z) * c4.z + sigf(i4.z) * tanhf(t4.z);
    cn.w = sigf(f4.w) * c4.w + sigf(i4.w) * tanhf(t4.w);
    hn.x = sigf(o4.x) * tanhf(cn.x);
    hn.y = sigf(o4.y) * tanhf(cn.y);
    hn.z = sigf(o4.z) * tanhf(cn.z);
    hn.w = sigf(o4.w) * tanhf(cn.w);

    *(float4*)&c_out[(size_t)r * HH + j] = cn;
    *(float4*)&h_out[(size_t)r * HH + j] = hn;
}

// ----------------------------------------------------------------------------
extern "C" void kernel_launch(void* const* d_in, const int* in_sizes, int n_in,
                              void* d_out, int out_size) {
    const float* x   = (const float*)d_in[0];
    const float* h0  = (const float*)d_in[1];
    const float* h1  = (const float*)d_in[2];
    const float* c0  = (const float*)d_in[3];
    const float* c1  = (const float*)d_in[4];
    const float* m0  = (const float*)d_in[5];
    const float* m1  = (const float*)d_in[6];
    const float* Wf0 = (const float*)d_in[7];  const float* bf0 = (const float*)d_in[8];
    const float* Wi0 = (const float*)d_in[9];  const float* bi0 = (const float*)d_in[10];
    const float* Wc0 = (const float*)d_in[11]; const float* bc0 = (const float*)d_in[12];
    const float* Wo0 = (const float*)d_in[13]; const float* bo0 = (const float*)d_in[14];
    const float* Wf1 = (const float*)d_in[15]; const float* bf1 = (const float*)d_in[16];
    const float* Wi1 = (const float*)d_in[17]; const float* bi1 = (const float*)d_in[18];
    const float* Wc1 = (const float*)d_in[19]; const float* bc1 = (const float*)d_in[20];
    const float* Wo1 = (const float*)d_in[21]; const float* bo1 = (const float*)d_in[22];
    const float* Wm1 = (const float*)d_in[23]; const float* bm1 = (const float*)d_in[24];
    const float* Wm2 = (const float*)d_in[25]; const float* bm2 = (const float*)d_in[26];

    float* gbuf; cudaGetSymbolAddress((void**)&gbuf, g_gbuf);
    float* tbuf; cudaGetSymbolAddress((void**)&tbuf, g_tbuf);

    float* out = (float*)d_out;
    float* h0n = out + (size_t)BB * OO;
    float* h1n = h0n + (size_t)BB * HH;
    float* c0n = h1n + (size_t)BB * HH;
    float* c1n = c0n + (size_t)BB * HH;

    const dim3 gGate(4096 / BN, BB / BM);       // 32 x 64
    const dim3 gM1(DMM / BN, BB / BM);          // 16 x 64
    const dim3 gM2(OO / BN, BB / BM);           //  2 x 64
    const int  lstmBlocks = (BB * HH / 4) / 256;

    // ---- layer 0: g = [x | h0*m0] @ [Wf0|Wi0|Wc0|Wo0] + b ----
    GemmArgs a0;
    a0.A0 = x;   a0.Ma0 = nullptr; a0.K0 = DD;
    a0.A1 = h0;  a0.Ma1 = m0;      a0.K1 = HH;
    a0.W0 = Wf0; a0.W1 = Wi0; a0.W2 = Wc0; a0.W3 = Wo0;
    a0.b0 = bf0; a0.b1 = bi0; a0.b2 = bc0; a0.b3 = bo0;
    a0.Nper = HH; a0.C = gbuf; a0.N = 4096;
    gemm_kernel<<<gGate, NT>>>(a0);
    lstm_cell_kernel<<<lstmBlocks, 256>>>(gbuf, c0, h0n, c0n);

    // ---- layer 1: g = [h0n*m0 | h1*m1] @ [Wf1|Wi1|Wc1|Wo1] + b ----
    GemmArgs a1;
    a1.A0 = h0n; a1.Ma0 = m0; a1.K0 = HH;
    a1.A1 = h1;  a1.Ma1 = m1; a1.K1 = HH;
    a1.W0 = Wf1; a1.W1 = Wi1; a1.W2 = Wc1; a1.W3 = Wo1;
    a1.b0 = bf1; a1.b1 = bi1; a1.b2 = bc1; a1.b3 = bo1;
    a1.Nper = HH; a1.C = gbuf; a1.N = 4096;
    gemm_kernel<<<gGate, NT>>>(a1);
    lstm_cell_kernel<<<lstmBlocks, 256>>>(gbuf, c1, h1n, c1n);

    // ---- MLP: t = h1n @ Wm1 + bm1 ; out = t @ Wm2 + bm2 ----
    GemmArgs a2;
    a2.A0 = h1n; a2.Ma0 = nullptr; a2.K0 = HH;
    a2.A1 = nullptr; a2.Ma1 = nullptr; a2.K1 = 0;
    a2.W0 = Wm1; a2.W1 = Wm1; a2.W2 = Wm1; a2.W3 = Wm1;
    a2.b0 = bm1; a2.b1 = bm1; a2.b2 = bm1; a2.b3 = bm1;
    a2.Nper = DMM; a2.C = tbuf; a2.N = DMM;
    gemm_kernel<<<gM1, NT>>>(a2);

    GemmArgs a3;
    a3.A0 = tbuf; a3.Ma0 = nullptr; a3.K0 = DMM;
    a3.A1 = nullptr; a3.Ma1 = nullptr; a3.K1 = 0;
    a3.W0 = Wm2; a3.W1 = Wm2; a3.W2 = Wm2; a3.W3 = Wm2;
    a3.b0 = bm2; a3.b1 = bm2; a3.b2 = bm2; a3.b3 = bm2;
    a3.Nper = OO; a3.C = out; a3.N = OO;
    gemm_kernel<<<gM2, NT>>>(a3);
}

// round 5
// speedup vs baseline: 2.5825x; 2.5825x over previous
#include <cuda_runtime.h>
#include <cuda_bf16.h>
#include <math.h>
#include <stdint.h>

// ----------------------------------------------------------------------------
// LSTM_88210038325547 on sm_100 (base target, no 'a' features):
// bf16x3-split GEMMs via mma.sync.m16n8k16 + cp.async pipeline.
//   B=8192, D=512, H=1024, DM=2048, O=256
// Outputs: out [B,O], h0n [B,H], h1n [B,H], c0n [B,H], c1n [B,H]
// ----------------------------------------------------------------------------

#define BB   8192
#define DD   512
#define HH   1024
#define DMM  2048
#define OO   256

// GEMM tile config
#define GM 128
#define GN 128
#define BK 32            // bf16 k per stage (64 bytes per row)
#define GT 256           // 8 warps
#define STAGES 3
#define STAGE_BYTES 32768   // Ah 8K | Al 8K | Bh 8K | Bl 8K
#define SMEM_GEMM (STAGES * STAGE_BYTES)

// ---------------------------------------------------------------------------
// Scratch (static device memory: allocation-guard safe)
// ---------------------------------------------------------------------------
__device__ __align__(256) float g_gbuf[(size_t)BB * 4096];
__device__ __align__(256) float g_tbuf[(size_t)BB * DMM];

__device__ __align__(256) __nv_bfloat16 g_A0h[(size_t)BB * 1536];
__device__ __align__(256) __nv_bfloat16 g_A0l[(size_t)BB * 1536];
__device__ __align__(256) __nv_bfloat16 g_A1h[(size_t)BB * 2048];
__device__ __align__(256) __nv_bfloat16 g_A1l[(size_t)BB * 2048];
__device__ __align__(256) __nv_bfloat16 g_A2h[(size_t)BB * 1024];
__device__ __align__(256) __nv_bfloat16 g_A2l[(size_t)BB * 1024];
__device__ __align__(256) __nv_bfloat16 g_A3h[(size_t)BB * 2048];
__device__ __align__(256) __nv_bfloat16 g_A3l[(size_t)BB * 2048];

__device__ __align__(256) __nv_bfloat16 g_W0h[(size_t)4096 * 1536];
__device__ __align__(256) __nv_bfloat16 g_W0l[(size_t)4096 * 1536];
__device__ __align__(256) __nv_bfloat16 g_W1h[(size_t)4096 * 2048];
__device__ __align__(256) __nv_bfloat16 g_W1l[(size_t)4096 * 2048];
__device__ __align__(256) __nv_bfloat16 g_Wm1h[(size_t)2048 * 1024];
__device__ __align__(256) __nv_bfloat16 g_Wm1l[(size_t)2048 * 1024];
__device__ __align__(256) __nv_bfloat16 g_Wm2h[(size_t)256 * 2048];
__device__ __align__(256) __nv_bfloat16 g_Wm2l[(size_t)256 * 2048];

__device__ float g_bias0[4096];
__device__ float g_bias1[4096];

// ---------------------------------------------------------------------------
// PTX helpers (sm_80-era only: valid under compute_100 base target)
// ---------------------------------------------------------------------------
__device__ __forceinline__ uint32_t smem_to_u32(const void* p) {
    uint32_t a;
    asm("{ .reg .u64 t; cvta.to.shared.u64 t, %1; cvt.u32.u64 %0, t; }"
        : "=r"(a) : "l"(p));
    return a;
}

__device__ __forceinline__ void cp16(uint32_t smem, const void* gmem) {
    asm volatile("cp.async.cg.shared.global [%0], [%1], 16;" :: "r"(smem), "l"(gmem));
}
#define CP_COMMIT() asm volatile("cp.async.commit_group;" ::: "memory")
#define CP_WAIT(n)  asm volatile("cp.async.wait_group %0;" :: "n"(n) : "memory")

__device__ __forceinline__ void ldsm_x4(uint32_t* r, uint32_t addr) {
    asm volatile("ldmatrix.sync.aligned.m8n8.x4.shared.b16 {%0,%1,%2,%3}, [%4];"
                 : "=r"(r[0]), "=r"(r[1]), "=r"(r[2]), "=r"(r[3]) : "r"(addr));
}
__device__ __forceinline__ void ldsm_x2(uint32_t* r, uint32_t addr) {
    asm volatile("ldmatrix.sync.aligned.m8n8.x2.shared.b16 {%0,%1}, [%2];"
                 : "=r"(r[0]), "=r"(r[1]) : "r"(addr));
}
__device__ __forceinline__ void mma_bf16(float* d, const uint32_t* a, const uint32_t* b) {
    asm volatile(
        "mma.sync.aligned.m16n8k16.row.col.f32.bf16.bf16.f32 "
        "{%0,%1,%2,%3}, {%4,%5,%6,%7}, {%8,%9}, {%0,%1,%2,%3};"
        : "+f"(d[0]), "+f"(d[1]), "+f"(d[2]), "+f"(d[3])
        : "r"(a[0]), "r"(a[1]), "r"(a[2]), "r"(a[3]), "r"(b[0]), "r"(b[1]));
}

// ---------------------------------------------------------------------------
// GEMM: C[8192, N] = A @ B^T + bias    (A:[M,K], B:[N,K], both bf16 hi/lo)
// grid = (N/128, 64), 256 threads. 3-term split: Ah*Bh + Ah*Bl + Al*Bh.
// smem swizzle: chunk' = chunk ^ ((row&7)>>1)  (conflict-free for ldmatrix)
// ---------------------------------------------------------------------------
__global__ void __launch_bounds__(GT, 1)
gemm_tc(const __nv_bfloat16* __restrict__ Ah, const __nv_bfloat16* __restrict__ Al,
        const __nv_bfloat16* __restrict__ Bh, const __nv_bfloat16* __restrict__ Bl,
        const float* __restrict__ bias, float* __restrict__ C, int ldC, int K)
{
    extern __shared__ char smem[];
    const uint32_t sbase = smem_to_u32(smem);

    const int tid    = threadIdx.x;
    const int lane   = tid & 31;
    const int wid    = tid >> 5;
    const int m_base = blockIdx.y * GM;
    const int n_base = blockIdx.x * GN;
    const int m_off  = (wid & 1) * 64;     // warp m sub-tile
    const int n_off  = (wid >> 1) * 32;    // warp n sub-tile

    // --- cp.async stage loader: 8 chunks (16B) per thread per stage ---
    auto load_stage = [&](int stg, int kt) {
        const uint32_t sb = sbase + stg * STAGE_BYTES;
        const int k0 = kt * BK;
#pragma unroll
        for (int u = 0; u < 2; u++) {
            const int c   = tid * 2 + u;       // 0..511
            const int row = c >> 2;
            const int kc  = c & 3;
            const uint32_t so = (uint32_t)(row * 64 + ((kc ^ ((row & 7) >> 1)) << 4));
            const size_t ga = (size_t)(m_base + row) * K + k0 + kc * 8;
            const size_t gb = (size_t)(n_base + row) * K + k0 + kc * 8;
            cp16(sb +         so, Ah + ga);
            cp16(sb +  8192 + so, Al + ga);
            cp16(sb + 16384 + so, Bh + gb);
            cp16(sb + 24576 + so, Bl + gb);
        }
    };

    // --- per-lane ldmatrix address components (hoisted) ---
    int rowA[4], swA[4], cA[4];
    int rowB[4], swB[4], cB[4];
    const int hsa = lane >> 4;          // A k-half select
    const int hsb = (lane >> 3) & 1;    // B k-half select
#pragma unroll
    for (int i = 0; i < 4; i++) {
        rowA[i] = m_off + i * 16 + (lane & 15);
        swA[i]  = (rowA[i] & 7) >> 1;
        cA[i]   = rowA[i] * 64;
        rowB[i] = n_off + i * 8 + (lane & 7);
        swB[i]  = (rowB[i] & 7) >> 1;
        cB[i]   = rowB[i] * 64;
    }

    float acc[4][4][4];
#pragma unroll
    for (int i = 0; i < 4; i++)
#pragma unroll
        for (int j = 0; j < 4; j++)
#pragma unroll
            for (int v = 0; v < 4; v++) acc[i][j][v] = 0.f;

    const int nk = K / BK;

    // prologue: stages 0,1
    load_stage(0, 0); CP_COMMIT();
    load_stage(1, 1); CP_COMMIT();

    for (int t = 0; t < nk; t++) {
        __syncthreads();                       // stage (t+2)%3 free to overwrite
        if (t + 2 < nk) load_stage((t + 2) % STAGES, t + 2);
        CP_COMMIT();
        CP_WAIT(2);                            // group t complete
        __syncthreads();                       // stage t visible to all warps

        const uint32_t sb = sbase + (t % STAGES) * STAGE_BYTES;
#pragma unroll
        for (int s = 0; s < 2; s++) {          // two k16 steps per BK=32
            const int s2 = s << 1;
            uint32_t ah[4][4], al[4][4], bh[4][2], bl[4][2];
#pragma unroll
            for (int i = 0; i < 4; i++) {
                const uint32_t off = cA[i] + (((s2 + hsa) ^ swA[i]) << 4);
                ldsm_x4(ah[i], sb + off);
                ldsm_x4(al[i], sb + 8192 + off);
            }
#pragma unroll
            for (int j = 0; j < 4; j++) {
                const uint32_t off = cB[j] + (((s2 + hsb) ^ swB[j]) << 4);
                ldsm_x2(bh[j], sb + 16384 + off);
                ldsm_x2(bl[j], sb + 24576 + off);
            }
#pragma unroll
            for (int i = 0; i < 4; i++)
#pragma unroll
                for (int j = 0; j < 4; j++) {
                    mma_bf16(acc[i][j], ah[i], bh[j]);
                    mma_bf16(acc[i][j], ah[i], bl[j]);
                    mma_bf16(acc[i][j], al[i], bh[j]);
                }
        }
    }

    // epilogue: + bias, float2 stores
#pragma unroll
    for (int i = 0; i < 4; i++) {
        const int r0 = m_base + m_off + i * 16 + (lane >> 2);
#pragma unroll
        for (int j = 0; j < 4; j++) {
            const int cc = n_base + n_off + j * 8 + (lane & 3) * 2;
            const float b0 = bias[cc], b1 = bias[cc + 1];
            float2 v0 = make_float2(acc[i][j][0] + b0, acc[i][j][1] + b1);
            float2 v1 = make_float2(acc[i][j][2] + b0, acc[i][j][3] + b1);
            *(float2*)&C[(size_t)r0 * ldC + cc]       = v0;
            *(float2*)&C[(size_t)(r0 + 8) * ldC + cc] = v1;
        }
    }
}

// ---------------------------------------------------------------------------
// Weight transpose + hi/lo split: W [K,N] fp32 -> Wt_hi/lo [noff+N rows][ldt]
// ---------------------------------------------------------------------------
__global__ void transpose_split_kernel(const float* __restrict__ W, int K, int N,
                                       __nv_bfloat16* __restrict__ th,
                                       __nv_bfloat16* __restrict__ tl,
                                       int noff, int ldt)
{
    __shared__ float tile[32][33];
    const int k0 = blockIdx.y * 32, n0 = blockIdx.x * 32;
    const int tx = threadIdx.x, ty = threadIdx.y;
#pragma unroll
    for (int i = 0; i < 4; i++)
        tile[ty + i * 8][tx] = W[(size_t)(k0 + ty + i * 8) * N + n0 + tx];
    __syncthreads();
#pragma unroll
    for (int i = 0; i < 4; i++) {
        const int n = ty + i * 8;
        const float v = tile[tx][n];
        const __nv_bfloat16 h = __float2bfloat16(v);
        const float lo = v - __bfloat162float(h);
        const size_t o = (size_t)(noff + n0 + n) * ldt + k0 + tx;
        th[o] = h;
        tl[o] = __float2bfloat16(lo);
    }
}

// ---------------------------------------------------------------------------
// Activation hi/lo split (optional elementwise mask): fp32 [rows,C] -> bf16x2
// ---------------------------------------------------------------------------
__global__ void split_kernel(const float* __restrict__ in, const float* __restrict__ mask,
                             int C, __nv_bfloat16* __restrict__ oh,
                             __nv_bfloat16* __restrict__ ol, int ldo, int coff)
{
    const int idx = blockIdx.x * blockDim.x + threadIdx.x;
    const int cpv = C >> 2;
    const int r = idx / cpv;
    const int c = (idx - r * cpv) << 2;
    const size_t gi = (size_t)r * C + c;
    float4 v = *(const float4*)(in + gi);
    if (mask) {
        const float4 m = *(const float4*)(mask + gi);
        v.x *= m.x; v.y *= m.y; v.z *= m.z; v.w *= m.w;
    }
    const float vv[4] = {v.x, v.y, v.z, v.w};
    __nv_bfloat16 hh[4], ll[4];
#pragma unroll
    for (int i = 0; i < 4; i++) {
        hh[i] = __float2bfloat16(vv[i]);
        ll[i] = __float2bfloat16(vv[i] - __bfloat162float(hh[i]));
    }
    const size_t o = (size_t)r * ldo + coff + c;
    *(__nv_bfloat162*)&oh[o]     = __nv_bfloat162(hh[0], hh[1]);
    *(__nv_bfloat162*)&oh[o + 2] = __nv_bfloat162(hh[2], hh[3]);
    *(__nv_bfloat162*)&ol[o]     = __nv_bfloat162(ll[0], ll[1]);
    *(__nv_bfloat162*)&ol[o + 2] = __nv_bfloat162(ll[2], ll[3]);
}

// ---------------------------------------------------------------------------
// LSTM cell: gates [B,4096] -> h_new/c_new fp32, plus bf16 hi/lo of h_new*mask
// ---------------------------------------------------------------------------
__device__ __forceinline__ float sigf(float x) { return 1.f / (1.f + __expf(-x)); }

__global__ void lstm_cell_kernel(const float* __restrict__ g, const float* __restrict__ c,
                                 const float* __restrict__ mask,
                                 float* __restrict__ h_out, float* __restrict__ c_out,
                                 __nv_bfloat16* __restrict__ oh, __nv_bfloat16* __restrict__ ol,
                                 int ldo, int coff)
{
    const int idx = blockIdx.x * blockDim.x + threadIdx.x;   // over B*H/4
    const int r = idx >> 8;
    const int j = (idx & 255) << 2;
    const size_t gb = (size_t)r * 4096 + j;
    const float4 f4 = *(const float4*)&g[gb];
    const float4 i4 = *(const float4*)&g[gb + 1024];
    const float4 t4 = *(const float4*)&g[gb + 2048];
    const float4 o4 = *(const float4*)&g[gb + 3072];
    const float4 c4 = *(const float4*)&c[(size_t)r * HH + j];

    float4 cn, hn;
    cn.x = sigf(f4.x) * c4.x + sigf(i4.x) * tanhf(t4.x);
    cn.y = sigf(f4.y) * c4.y + sigf(i4.y) * tanhf(t4.y);
    cn.z = sigf(f4.z) * c4.z + sigf(i4.z) * tanhf(t4.z);
    cn.w = sigf(f4.w) * c4.w + sigf(i4.w) * tanhf(t4.w);
    hn.x = sigf(o4.x) * tanhf(cn.x);
    hn.y = sigf(o4.y) * tanhf(cn.y);
    hn.z = sigf(o4.z) * tanhf(cn.z);
    hn.w = sigf(o4.w) * tanhf(cn.w);

    *(float4*)&c_out[(size_t)r * HH + j] = cn;
    *(float4*)&h_out[(size_t)r * HH + j] = hn;

    float4 hv = hn;
    if (mask) {
        const float4 m = *(const float4*)&mask[(size_t)r * HH + j];
        hv.x *= m.x; hv.y *= m.y; hv.z *= m.z; hv.w *= m.w;
    }
    const float vv[4] = {hv.x, hv.y, hv.z, hv.w};
    __nv_bfloat16 hh[4], ll[4];
#pragma unroll
    for (int i = 0; i < 4; i++) {
        hh[i] = __float2bfloat16(vv[i]);
        ll[i] = __float2bfloat16(vv[i] - __bfloat162float(hh[i]));
    }
    const size_t o = (size_t)r * ldo + coff + j;
    *(__nv_bfloat162*)&oh[o]     = __nv_bfloat162(hh[0], hh[1]);
    *(__nv_bfloat162*)&oh[o + 2] = __nv_bfloat162(hh[2], hh[3]);
    *(__nv_bfloat162*)&ol[o]     = __nv_bfloat162(ll[0], ll[1]);
    *(__nv_bfloat162*)&ol[o + 2] = __nv_bfloat162(ll[2], ll[3]);
}

// ---------------------------------------------------------------------------
__global__ void biascat_kernel(const float* __restrict__ a, const float* __restrict__ b,
                               const float* __restrict__ c, const float* __restrict__ d,
                               float* __restrict__ o)
{
    const int i = blockIdx.x * blockDim.x + threadIdx.x;   // < 4096
    float v;
    if (i < 1024)      v = a[i];
    else if (i < 2048) v = b[i - 1024];
    else if (i < 3072) v = c[i - 2048];
    else               v = d[i - 3072];
    o[i] = v;
}

// ---------------------------------------------------------------------------
extern "C" void kernel_launch(void* const* d_in, const int* in_sizes, int n_in,
                              void* d_out, int out_size) {
    const float* x   = (const float*)d_in[0];
    const float* h0  = (const float*)d_in[1];
    const float* h1  = (const float*)d_in[2];
    const float* c0  = (const float*)d_in[3];
    const float* c1  = (const float*)d_in[4];
    const float* m0  = (const float*)d_in[5];
    const float* m1  = (const float*)d_in[6];
    const float* Wf0 = (const float*)d_in[7];  const float* bf0 = (const float*)d_in[8];
    const float* Wi0 = (const float*)d_in[9];  const float* bi0 = (const float*)d_in[10];
    const float* Wc0 = (const float*)d_in[11]; const float* bc0 = (const float*)d_in[12];
    const float* Wo0 = (const float*)d_in[13]; const float* bo0 = (const float*)d_in[14];
    const float* Wf1 = (const float*)d_in[15]; const float* bf1 = (const float*)d_in[16];
    const float* Wi1 = (const float*)d_in[17]; const float* bi1 = (const float*)d_in[18];
    const float* Wc1 = (const float*)d_in[19]; const float* bc1 = (const float*)d_in[20];
    const float* Wo1 = (const float*)d_in[21]; const float* bo1 = (const float*)d_in[22];
    const float* Wm1 = (const float*)d_in[23]; const float* bm1 = (const float*)d_in[24];
    const float* Wm2 = (const float*)d_in[25]; const float* bm2 = (const float*)d_in[26];

    cudaFuncSetAttribute(gemm_tc, cudaFuncAttributeMaxDynamicSharedMemorySize, SMEM_GEMM);

    float *gbuf, *tbuf, *bias0, *bias1;
    cudaGetSymbolAddress((void**)&gbuf, g_gbuf);
    cudaGetSymbolAddress((void**)&tbuf, g_tbuf);
    cudaGetSymbolAddress((void**)&bias0, g_bias0);
    cudaGetSymbolAddress((void**)&bias1, g_bias1);

    __nv_bfloat16 *A0h, *A0l, *A1h, *A1l, *A2h, *A2l, *A3h, *A3l;
    __nv_bfloat16 *W0h, *W0l, *W1h, *W1l, *Wm1h, *Wm1l, *Wm2h, *Wm2l;
    cudaGetSymbolAddress((void**)&A0h, g_A0h);   cudaGetSymbolAddress((void**)&A0l, g_A0l);
    cudaGetSymbolAddress((void**)&A1h, g_A1h);   cudaGetSymbolAddress((void**)&A1l, g_A1l);
    cudaGetSymbolAddress((void**)&A2h, g_A2h);   cudaGetSymbolAddress((void**)&A2l, g_A2l);
    cudaGetSymbolAddress((void**)&A3h, g_A3h);   cudaGetSymbolAddress((void**)&A3l, g_A3l);
    cudaGetSymbolAddress((void**)&W0h, g_W0h);   cudaGetSymbolAddress((void**)&W0l, g_W0l);
    cudaGetSymbolAddress((void**)&W1h, g_W1h);   cudaGetSymbolAddress((void**)&W1l, g_W1l);
    cudaGetSymbolAddress((void**)&Wm1h, g_Wm1h); cudaGetSymbolAddress((void**)&Wm1l, g_Wm1l);
    cudaGetSymbolAddress((void**)&Wm2h, g_Wm2h); cudaGetSymbolAddress((void**)&Wm2l, g_Wm2l);

    float* out = (float*)d_out;
    float* h0n = out + (size_t)BB * OO;
    float* h1n = h0n + (size_t)BB * HH;
    float* c0n = h1n + (size_t)BB * HH;
    float* c1n = c0n + (size_t)BB * HH;

    const dim3 tb(32, 8);

    // ---- weight pre-pass: transpose + hi/lo split ----
    transpose_split_kernel<<<dim3(32, 48), tb>>>(Wf0, 1536, 1024, W0h, W0l, 0,    1536);
    transpose_split_kernel<<<dim3(32, 48), tb>>>(Wi0, 1536, 1024, W0h, W0l, 1024, 1536);
    transpose_split_kernel<<<dim3(32, 48), tb>>>(Wc0, 1536, 1024, W0h, W0l, 2048, 1536);
    transpose_split_kernel<<<dim3(32, 48), tb>>>(Wo0, 1536, 1024, W0h, W0l, 3072, 1536);
    transpose_split_kernel<<<dim3(32, 64), tb>>>(Wf1, 2048, 1024, W1h, W1l, 0,    2048);
    transpose_split_kernel<<<dim3(32, 64), tb>>>(Wi1, 2048, 1024, W1h, W1l, 1024, 2048);
    transpose_split_kernel<<<dim3(32, 64), tb>>>(Wc1, 2048, 1024, W1h, W1l, 2048, 2048);
    transpose_split_kernel<<<dim3(32, 64), tb>>>(Wo1, 2048, 1024, W1h, W1l, 3072, 2048);
    transpose_split_kernel<<<dim3(64, 32), tb>>>(Wm1, 1024, 2048, Wm1h, Wm1l, 0, 1024);
    transpose_split_kernel<<<dim3(8,  64), tb>>>(Wm2, 2048, 256,  Wm2h, Wm2l, 0, 2048);
    biascat_kernel<<<16, 256>>>(bf0, bi0, bc0, bo0, bias0);
    biascat_kernel<<<16, 256>>>(bf1, bi1, bc1, bo1, bias1);

    // ---- activation pre-pass ----
    split_kernel<<<4096, 256>>>(x,  nullptr, 512,  A0h, A0l, 1536, 0);
    split_kernel<<<8192, 256>>>(h0, m0,      1024, A0h, A0l, 1536, 512);
    split_kernel<<<8192, 256>>>(h1, m1,      1024, A1h, A1l, 2048, 1024);

    // ---- layer 0: g = [x | h0*m0] @ W0^T + b0 ----
    gemm_tc<<<dim3(32, 64), GT, SMEM_GEMM>>>(A0h, A0l, W0h, W0l, bias0, gbuf, 4096, 1536);
    lstm_cell_kernel<<<8192, 256>>>(gbuf, c0, m0, h0n, c0n, A1h, A1l, 2048, 0);

    // ---- layer 1: g = [h0n*m0 | h1*m1] @ W1^T + b1 ----
    gemm_tc<<<dim3(32, 64), GT, SMEM_GEMM>>>(A1h, A1l, W1h, W1l, bias1, gbuf, 4096, 2048);
    lstm_cell_kernel<<<8192, 256>>>(gbuf, c1, nullptr, h1n, c1n, A2h, A2l, 1024, 0);

    // ---- MLP ----
    gemm_tc<<<dim3(16, 64), GT, SMEM_GEMM>>>(A2h, A2l, Wm1h, Wm1l, bm1, tbuf, 2048, 1024);
    split_kernel<<<16384, 256>>>(tbuf, nullptr, 2048, A3h, A3l, 2048, 0);
    gemm_tc<<<dim3(2, 64), GT, SMEM_GEMM>>>(A3h, A3l, Wm2h, Wm2l, bm2, out, 256, 2048);
}

// round 7
// speedup vs baseline: 2.5834x; 1.0003x over previous
#include <cuda_runtime.h>
#include <cuda_bf16.h>
#include <math.h>
#include <stdint.h>

// ----------------------------------------------------------------------------
// LSTM_88210038325547 on sm_100 (base target, no 'a' features):
// bf16x3-split GEMMs via mma.sync.m16n8k16 + cp.async pipeline.
//   B=8192, D=512, H=1024, DM=2048, O=256
// Outputs: out [B,O], h0n [B,H], h1n [B,H], c0n [B,H], c1n [B,H]
// ----------------------------------------------------------------------------

#define BB   8192
#define DD   512
#define HH   1024
#define DMM  2048
#define OO   256

// GEMM tile config
#define GM 128
#define GN 128
#define BK 32            // bf16 k per stage (64 bytes per row)
#define GT 256           // 8 warps
#define STAGES 3
#define STAGE_BYTES 32768   // Ah 8K | Al 8K | Bh 8K | Bl 8K
#define SMEM_GEMM (STAGES * STAGE_BYTES)

// ---------------------------------------------------------------------------
// Scratch (static device memory: allocation-guard safe)
// ---------------------------------------------------------------------------
__device__ __align__(256) float g_gbuf[(size_t)BB * 4096];
__device__ __align__(256) float g_tbuf[(size_t)BB * DMM];

__device__ __align__(256) __nv_bfloat16 g_A0h[(size_t)BB * 1536];
__device__ __align__(256) __nv_bfloat16 g_A0l[(size_t)BB * 1536];
__device__ __align__(256) __nv_bfloat16 g_A1h[(size_t)BB * 2048];
__device__ __align__(256) __nv_bfloat16 g_A1l[(size_t)BB * 2048];
__device__ __align__(256) __nv_bfloat16 g_A2h[(size_t)BB * 1024];
__device__ __align__(256) __nv_bfloat16 g_A2l[(size_t)BB * 1024];
__device__ __align__(256) __nv_bfloat16 g_A3h[(size_t)BB * 2048];
__device__ __align__(256) __nv_bfloat16 g_A3l[(size_t)BB * 2048];

__device__ __align__(256) __nv_bfloat16 g_W0h[(size_t)4096 * 1536];
__device__ __align__(256) __nv_bfloat16 g_W0l[(size_t)4096 * 1536];
__device__ __align__(256) __nv_bfloat16 g_W1h[(size_t)4096 * 2048];
__device__ __align__(256) __nv_bfloat16 g_W1l[(size_t)4096 * 2048];
__device__ __align__(256) __nv_bfloat16 g_Wm1h[(size_t)2048 * 1024];
__device__ __align__(256) __nv_bfloat16 g_Wm1l[(size_t)2048 * 1024];
__device__ __align__(256) __nv_bfloat16 g_Wm2h[(size_t)256 * 2048];
__device__ __align__(256) __nv_bfloat16 g_Wm2l[(size_t)256 * 2048];

__device__ float g_bias0[4096];
__device__ float g_bias1[4096];

// ---------------------------------------------------------------------------
// PTX helpers (sm_80-era only: valid under compute_100 base target)
// ---------------------------------------------------------------------------
__device__ __forceinline__ uint32_t smem_to_u32(const void* p) {
    uint32_t a;
    asm("{ .reg .u64 t; cvta.to.shared.u64 t, %1; cvt.u32.u64 %0, t; }"
        : "=r"(a) : "l"(p));
    return a;
}

__device__ __forceinline__ void cp16(uint32_t smem, const void* gmem) {
    asm volatile("cp.async.cg.shared.global [%0], [%1], 16;" :: "r"(smem), "l"(gmem));
}
#define CP_COMMIT() asm volatile("cp.async.commit_group;" ::: "memory")
#define CP_WAIT(n)  asm volatile("cp.async.wait_group %0;" :: "n"(n) : "memory")

__device__ __forceinline__ void ldsm_x4(uint32_t* r, uint32_t addr) {
    asm volatile("ldmatrix.sync.aligned.m8n8.x4.shared.b16 {%0,%1,%2,%3}, [%4];"
                 : "=r"(r[0]), "=r"(r[1]), "=r"(r[2]), "=r"(r[3]) : "r"(addr));
}
__device__ __forceinline__ void ldsm_x2(uint32_t* r, uint32_t addr) {
    asm volatile("ldmatrix.sync.aligned.m8n8.x2.shared.b16 {%0,%1}, [%2];"
                 : "=r"(r[0]), "=r"(r[1]) : "r"(addr));
}
__device__ __forceinline__ void mma_bf16(float* d, const uint32_t* a, const uint32_t* b) {
    asm volatile(
        "mma.sync.aligned.m16n8k16.row.col.f32.bf16.bf16.f32 "
        "{%0,%1,%2,%3}, {%4,%5,%6,%7}, {%8,%9}, {%0,%1,%2,%3};"
        : "+f"(d[0]), "+f"(d[1]), "+f"(d[2]), "+f"(d[3])
        : "r"(a[0]), "r"(a[1]), "r"(a[2]), "r"(a[3]), "r"(b[0]), "r"(b[1]));
}

// ---------------------------------------------------------------------------
// GEMM: C[8192, N] = A @ B^T + bias    (A:[M,K], B:[N,K], both bf16 hi/lo)
// grid = (N/128, 64), 256 threads. 3-term split: Ah*Bh + Ah*Bl + Al*Bh.
// smem swizzle: chunk' = chunk ^ ((row&7)>>1)  (conflict-free for ldmatrix)
// ---------------------------------------------------------------------------
__global__ void __launch_bounds__(GT, 1)
gemm_tc(const __nv_bfloat16* __restrict__ Ah, const __nv_bfloat16* __restrict__ Al,
        const __nv_bfloat16* __restrict__ Bh, const __nv_bfloat16* __restrict__ Bl,
        const float* __restrict__ bias, float* __restrict__ C, int ldC, int K)
{
    extern __shared__ char smem[];
    const uint32_t sbase = smem_to_u32(smem);

    const int tid    = threadIdx.x;
    const int lane   = tid & 31;
    const int wid    = tid >> 5;
    const int m_base = blockIdx.y * GM;
    const int n_base = blockIdx.x * GN;
    const int m_off  = (wid & 1) * 64;     // warp m sub-tile
    const int n_off  = (wid >> 1) * 32;    // warp n sub-tile

    // --- cp.async stage loader: 8 chunks (16B) per thread per stage ---
    auto load_stage = [&](int stg, int kt) {
        const uint32_t sb = sbase + stg * STAGE_BYTES;
        const int k0 = kt * BK;
#pragma unroll
        for (int u = 0; u < 2; u++) {
            const int c   = tid * 2 + u;       // 0..511
            const int row = c >> 2;
            const int kc  = c & 3;
            const uint32_t so = (uint32_t)(row * 64 + ((kc ^ ((row & 7) >> 1)) << 4));
            const size_t ga = (size_t)(m_base + row) * K + k0 + kc * 8;
            const size_t gb = (size_t)(n_base + row) * K + k0 + kc * 8;
            cp16(sb +         so, Ah + ga);
            cp16(sb +  8192 + so, Al + ga);
            cp16(sb + 16384 + so, Bh + gb);
            cp16(sb + 24576 + so, Bl + gb);
        }
    };

    // --- per-lane ldmatrix address components (hoisted) ---
    int rowA[4], swA[4], cA[4];
    int rowB[4], swB[4], cB[4];
    const int hsa = lane >> 4;          // A k-half select
    const int hsb = (lane >> 3) & 1;    // B k-half select
#pragma unroll
    for (int i = 0; i < 4; i++) {
        rowA[i] = m_off + i * 16 + (lane & 15);
        swA[i]  = (rowA[i] & 7) >> 1;
        cA[i]   = rowA[i] * 64;
        rowB[i] = n_off + i * 8 + (lane & 7);
        swB[i]  = (rowB[i] & 7) >> 1;
        cB[i]   = rowB[i] * 64;
    }

    float acc[4][4][4];
#pragma unroll
    for (int i = 0; i < 4; i++)
#pragma unroll
        for (int j = 0; j < 4; j++)
#pragma unroll
            for (int v = 0; v < 4; v++) acc[i][j][v] = 0.f;

    const int nk = K / BK;

    // prologue: stages 0,1
    load_stage(0, 0); CP_COMMIT();
    load_stage(1, 1); CP_COMMIT();

    for (int t = 0; t < nk; t++) {
        __syncthreads();                       // stage (t+2)%3 free to overwrite
        if (t + 2 < nk) load_stage((t + 2) % STAGES, t + 2);
        CP_COMMIT();
        CP_WAIT(2);                            // group t complete
        __syncthreads();                       // stage t visible to all warps

        const uint32_t sb = sbase + (t % STAGES) * STAGE_BYTES;
#pragma unroll
        for (int s = 0; s < 2; s++) {          // two k16 steps per BK=32
            const int s2 = s << 1;
            uint32_t ah[4][4], al[4][4], bh[4][2], bl[4][2];
#pragma unroll
            for (int i = 0; i < 4; i++) {
                const uint32_t off = cA[i] + (((s2 + hsa) ^ swA[i]) << 4);
                ldsm_x4(ah[i], sb + off);
                ldsm_x4(al[i], sb + 8192 + off);
            }
#pragma unroll
            for (int j = 0; j < 4; j++) {
                const uint32_t off = cB[j] + (((s2 + hsb) ^ swB[j]) << 4);
                ldsm_x2(bh[j], sb + 16384 + off);
                ldsm_x2(bl[j], sb + 24576 + off);
            }
#pragma unroll
            for (int i = 0; i < 4; i++)
#pragma unroll
                for (int j = 0; j < 4; j++) {
                    mma_bf16(acc[i][j], ah[i], bh[j]);
                    mma_bf16(acc[i][j], ah[i], bl[j]);
                    mma_bf16(acc[i][j], al[i], bh[j]);
                }
        }
    }

    // epilogue: + bias, float2 stores
#pragma unroll
    for (int i = 0; i < 4; i++) {
        const int r0 = m_base + m_off + i * 16 + (lane >> 2);
#pragma unroll
        for (int j = 0; j < 4; j++) {
            const int cc = n_base + n_off + j * 8 + (lane & 3) * 2;
            const float b0 = bias[cc], b1 = bias[cc + 1];
            float2 v0 = make_float2(acc[i][j][0] + b0, acc[i][j][1] + b1);
            float2 v1 = make_float2(acc[i][j][2] + b0, acc[i][j][3] + b1);
            *(float2*)&C[(size_t)r0 * ldC + cc]       = v0;
            *(float2*)&C[(size_t)(r0 + 8) * ldC + cc] = v1;
        }
    }
}

// ---------------------------------------------------------------------------
// Weight transpose + hi/lo split: W [K,N] fp32 -> Wt_hi/lo [noff+N rows][ldt]
// ---------------------------------------------------------------------------
__global__ void transpose_split_kernel(const float* __restrict__ W, int K, int N,
                                       __nv_bfloat16* __restrict__ th,
                                       __nv_bfloat16* __restrict__ tl,
                                       int noff, int ldt)
{
    __shared__ float tile[32][33];
    const int k0 = blockIdx.y * 32, n0 = blockIdx.x * 32;
    const int tx = threadIdx.x, ty = threadIdx.y;
#pragma unroll
    for (int i = 0; i < 4; i++)
        tile[ty + i * 8][tx] = W[(size_t)(k0 + ty + i * 8) * N + n0 + tx];
    __syncthreads();
#pragma unroll
    for (int i = 0; i < 4; i++) {
        const int n = ty + i * 8;
        const float v = tile[tx][n];
        const __nv_bfloat16 h = __float2bfloat16(v);
        const float lo = v - __bfloat162float(h);
        const size_t o = (size_t)(noff + n0 + n) * ldt + k0 + tx;
        th[o] = h;
        tl[o] = __float2bfloat16(lo);
    }
}

// ---------------------------------------------------------------------------
// Activation hi/lo split (optional elementwise mask): fp32 [rows,C] -> bf16x2
// ---------------------------------------------------------------------------
__global__ void split_kernel(const float* __restrict__ in, const float* __restrict__ mask,
                             int C, __nv_bfloat16* __restrict__ oh,
                             __nv_bfloat16* __restrict__ ol, int ldo, int coff)
{
    const int idx = blockIdx.x * blockDim.x + threadIdx.x;
    const int cpv = C >> 2;
    const int r = idx / cpv;
    const int c = (idx - r * cpv) << 2;
    const size_t gi = (size_t)r * C + c;
    float4 v = *(const float4*)(in + gi);
    if (mask) {
        const float4 m = *(const float4*)(mask + gi);
        v.x *= m.x; v.y *= m.y; v.z *= m.z; v.w *= m.w;
    }
    const float vv[4] = {v.x, v.y, v.z, v.w};
    __nv_bfloat16 hh[4], ll[4];
#pragma unroll
    for (int i = 0; i < 4; i++) {
        hh[i] = __float2bfloat16(vv[i]);
        ll[i] = __float2bfloat16(vv[i] - __bfloat162float(hh[i]));
    }
    const size_t o = (size_t)r * ldo + coff + c;
    *(__nv_bfloat162*)&oh[o]     = __nv_bfloat162(hh[0], hh[1]);
    *(__nv_bfloat162*)&oh[o + 2] = __nv_bfloat162(hh[2], hh[3]);
    *(__nv_bfloat162*)&ol[o]     = __nv_bfloat162(ll[0], ll[1]);
    *(__nv_bfloat162*)&ol[o + 2] = __nv_bfloat162(ll[2], ll[3]);
}

// ---------------------------------------------------------------------------
// LSTM cell: gates [B,4096] -> h_new/c_new fp32, plus bf16 hi/lo of h_new*mask
// ---------------------------------------------------------------------------
__device__ __forceinline__ float sigf(float x) { return 1.f / (1.f + __expf(-x)); }

__global__ void lstm_cell_kernel(const float* __restrict__ g, const float* __restrict__ c,
                                 const float* __restrict__ mask,
                                 float* __restrict__ h_out, float* __restrict__ c_out,
                                 __nv_bfloat16* __restrict__ oh, __nv_bfloat16* __restrict__ ol,
                                 int ldo, int coff)
{
    const int idx = blockIdx.x * blockDim.x + threadIdx.x;   // over B*H/4
    const int r = idx >> 8;
    const int j = (idx & 255) << 2;
    const size_t gb = (size_t)r * 4096 + j;
    const float4 f4 = *(const float4*)&g[gb];
    const float4 i4 = *(const float4*)&g[gb + 1024];
    const float4 t4 = *(const float4*)&g[gb + 2048];
    const float4 o4 = *(const float4*)&g[gb + 3072];
    const float4 c4 = *(const float4*)&c[(size_t)r * HH + j];

    float4 cn, hn;
    cn.x = sigf(f4.x) * c4.x + sigf(i4.x) * tanhf(t4.x);
    cn.y = sigf(f4.y) * c4.y + sigf(i4.y) * tanhf(t4.y);
    cn.z = sigf(f4.z) * c4.z + sigf(i4.z) * tanhf(t4.z);
    cn.w = sigf(f4.w) * c4.w + sigf(i4.w) * tanhf(t4.w);
    hn.x = sigf(o4.x) * tanhf(cn.x);
    hn.y = sigf(o4.y) * tanhf(cn.y);
    hn.z = sigf(o4.z) * tanhf(cn.z);
    hn.w = sigf(o4.w) * tanhf(cn.w);

    *(float4*)&c_out[(size_t)r * HH + j] = cn;
    *(float4*)&h_out[(size_t)r * HH + j] = hn;

    float4 hv = hn;
    if (mask) {
        const float4 m = *(const float4*)&mask[(size_t)r * HH + j];
        hv.x *= m.x; hv.y *= m.y; hv.z *= m.z; hv.w *= m.w;
    }
    const float vv[4] = {hv.x, hv.y, hv.z, hv.w};
    __nv_bfloat16 hh[4], ll[4];
#pragma unroll
    for (int i = 0; i < 4; i++) {
        hh[i] = __float2bfloat16(vv[i]);
        ll[i] = __float2bfloat16(vv[i] - __bfloat162float(hh[i]));
    }
    const size_t o = (size_t)r * ldo + coff + j;
    *(__nv_bfloat162*)&oh[o]     = __nv_bfloat162(hh[0], hh[1]);
    *(__nv_bfloat162*)&oh[o + 2] = __nv_bfloat162(hh[2], hh[3]);
    *(__nv_bfloat162*)&ol[o]     = __nv_bfloat162(ll[0], ll[1]);
    *(__nv_bfloat162*)&ol[o + 2] = __nv_bfloat162(ll[2], ll[3]);
}

// ---------------------------------------------------------------------------
__global__ void biascat_kernel(const float* __restrict__ a, const float* __restrict__ b,
                               const float* __restrict__ c, const float* __restrict__ d,
                               float* __restrict__ o)
{
    const int i = blockIdx.x * blockDim.x + threadIdx.x;   // < 4096
    float v;
    if (i < 1024)      v = a[i];
    else if (i < 2048) v = b[i - 1024];
    else if (i < 3072) v = c[i - 2048];
    else               v = d[i - 3072];
    o[i] = v;
}

// ---------------------------------------------------------------------------
extern "C" void kernel_launch(void* const* d_in, const int* in_sizes, int n_in,
                              void* d_out, int out_size) {
    const float* x   = (const float*)d_in[0];
    const float* h0  = (const float*)d_in[1];
    const float* h1  = (const float*)d_in[2];
    const float* c0  = (const float*)d_in[3];
    const float* c1  = (const float*)d_in[4];
    const float* m0  = (const float*)d_in[5];
    const float* m1  = (const float*)d_in[6];
    const float* Wf0 = (const float*)d_in[7];  const float* bf0 = (const float*)d_in[8];
    const float* Wi0 = (const float*)d_in[9];  const float* bi0 = (const float*)d_in[10];
    const float* Wc0 = (const float*)d_in[11]; const float* bc0 = (const float*)d_in[12];
    const float* Wo0 = (const float*)d_in[13]; const float* bo0 = (const float*)d_in[14];
    const float* Wf1 = (const float*)d_in[15]; const float* bf1 = (const float*)d_in[16];
    const float* Wi1 = (const float*)d_in[17]; const float* bi1 = (const float*)d_in[18];
    const float* Wc1 = (const float*)d_in[19]; const float* bc1 = (const float*)d_in[20];
    const float* Wo1 = (const float*)d_in[21]; const float* bo1 = (const float*)d_in[22];
    const float* Wm1 = (const float*)d_in[23]; const float* bm1 = (const float*)d_in[24];
    const float* Wm2 = (const float*)d_in[25]; const float* bm2 = (const float*)d_in[26];

    cudaFuncSetAttribute(gemm_tc, cudaFuncAttributeMaxDynamicSharedMemorySize, SMEM_GEMM);

    float *gbuf, *tbuf, *bias0, *bias1;
    cudaGetSymbolAddress((void**)&gbuf, g_gbuf);
    cudaGetSymbolAddress((void**)&tbuf, g_tbuf);
    cudaGetSymbolAddress((void**)&bias0, g_bias0);
    cudaGetSymbolAddress((void**)&bias1, g_bias1);

    __nv_bfloat16 *A0h, *A0l, *A1h, *A1l, *A2h, *A2l, *A3h, *A3l;
    __nv_bfloat16 *W0h, *W0l, *W1h, *W1l, *Wm1h, *Wm1l, *Wm2h, *Wm2l;
    cudaGetSymbolAddress((void**)&A0h, g_A0h);   cudaGetSymbolAddress((void**)&A0l, g_A0l);
    cudaGetSymbolAddress((void**)&A1h, g_A1h);   cudaGetSymbolAddress((void**)&A1l, g_A1l);
    cudaGetSymbolAddress((void**)&A2h, g_A2h);   cudaGetSymbolAddress((void**)&A2l, g_A2l);
    cudaGetSymbolAddress((void**)&A3h, g_A3h);   cudaGetSymbolAddress((void**)&A3l, g_A3l);
    cudaGetSymbolAddress((void**)&W0h, g_W0h);   cudaGetSymbolAddress((void**)&W0l, g_W0l);
    cudaGetSymbolAddress((void**)&W1h, g_W1h);   cudaGetSymbolAddress((void**)&W1l, g_W1l);
    cudaGetSymbolAddress((void**)&Wm1h, g_Wm1h); cudaGetSymbolAddress((void**)&Wm1l, g_Wm1l);
    cudaGetSymbolAddress((void**)&Wm2h, g_Wm2h); cudaGetSymbolAddress((void**)&Wm2l, g_Wm2l);

    float* out = (float*)d_out;
    float* h0n = out + (size_t)BB * OO;
    float* h1n = h0n + (size_t)BB * HH;
    float* c0n = h1n + (size_t)BB * HH;
    float* c1n = c0n + (size_t)BB * HH;

    const dim3 tb(32, 8);

    // ---- weight pre-pass: transpose + hi/lo split ----
    transpose_split_kernel<<<dim3(32, 48), tb>>>(Wf0, 1536, 1024, W0h, W0l, 0,    1536);
    transpose_split_kernel<<<dim3(32, 48), tb>>>(Wi0, 1536, 1024, W0h, W0l, 1024, 1536);
    transpose_split_kernel<<<dim3(32, 48), tb>>>(Wc0, 1536, 1024, W0h, W0l, 2048, 1536);
    transpose_split_kernel<<<dim3(32, 48), tb>>>(Wo0, 1536, 1024, W0h, W0l, 3072, 1536);
    transpose_split_kernel<<<dim3(32, 64), tb>>>(Wf1, 2048, 1024, W1h, W1l, 0,    2048);
    transpose_split_kernel<<<dim3(32, 64), tb>>>(Wi1, 2048, 1024, W1h, W1l, 1024, 2048);
    transpose_split_kernel<<<dim3(32, 64), tb>>>(Wc1, 2048, 1024, W1h, W1l, 2048, 2048);
    transpose_split_kernel<<<dim3(32, 64), tb>>>(Wo1, 2048, 1024, W1h, W1l, 3072, 2048);
    transpose_split_kernel<<<dim3(64, 32), tb>>>(Wm1, 1024, 2048, Wm1h, Wm1l, 0, 1024);
    transpose_split_kernel<<<dim3(8,  64), tb>>>(Wm2, 2048, 256,  Wm2h, Wm2l, 0, 2048);
    biascat_kernel<<<16, 256>>>(bf0, bi0, bc0, bo0, bias0);
    biascat_kernel<<<16, 256>>>(bf1, bi1, bc1, bo1, bias1);

    // ---- activation pre-pass ----
    split_kernel<<<4096, 256>>>(x,  nullptr, 512,  A0h, A0l, 1536, 0);
    split_kernel<<<8192, 256>>>(h0, m0,      1024, A0h, A0l, 1536, 512);
    split_kernel<<<8192, 256>>>(h1, m1,      1024, A1h, A1l, 2048, 1024);

    // ---- layer 0: g = [x | h0*m0] @ W0^T + b0 ----
    gemm_tc<<<dim3(32, 64), GT, SMEM_GEMM>>>(A0h, A0l, W0h, W0l, bias0, gbuf, 4096, 1536);
    lstm_cell_kernel<<<8192, 256>>>(gbuf, c0, m0, h0n, c0n, A1h, A1l, 2048, 0);

    // ---- layer 1: g = [h0n*m0 | h1*m1] @ W1^T + b1 ----
    gemm_tc<<<dim3(32, 64), GT, SMEM_GEMM>>>(A1h, A1l, W1h, W1l, bias1, gbuf, 4096, 2048);
    lstm_cell_kernel<<<8192, 256>>>(gbuf, c1, nullptr, h1n, c1n, A2h, A2l, 1024, 0);

    // ---- MLP ----
    gemm_tc<<<dim3(16, 64), GT, SMEM_GEMM>>>(A2h, A2l, Wm1h, Wm1l, bm1, tbuf, 2048, 1024);
    split_kernel<<<16384, 256>>>(tbuf, nullptr, 2048, A3h, A3l, 2048, 0);
    gemm_tc<<<dim3(2, 64), GT, SMEM_GEMM>>>(A3h, A3l, Wm2h, Wm2l, bm2, out, 256, 2048);
}